// round 6
// baseline (speedup 1.0000x reference)
#include <cuda_runtime.h>

// RipsLayer: pure gather of pairwise distances at given index pairs.
//
// Output layout (flattened tuple order, fp32):
//   [0, 2*F0)      finite_dgm0 rows: (0, dist)     -> float2 stores
//   [2*F0, +E0)    essential_dgm0: zeros
//   [.., +2*F1)    finite_dgm1 rows: (dist, dist)  -> odd float offset when
//                  E0 is odd, so scalar stores
//   [.., +E1)      essential_dgm1: one dist per row
//
// Work split (latency-bound, maximize per-thread MLP):
//   dgm0: 2 rows/thread (4 idx loads + 12 X loads front-batched)
//   dgm1: 1 row/thread  (one int4 idx load + 12 X loads)

__device__ __forceinline__ float pair_dist(const float* __restrict__ X,
                                           int a, int b) {
    float ax = __ldg(X + 3 * a + 0);
    float ay = __ldg(X + 3 * a + 1);
    float az = __ldg(X + 3 * a + 2);
    float bx = __ldg(X + 3 * b + 0);
    float by = __ldg(X + 3 * b + 1);
    float bz = __ldg(X + 3 * b + 2);
    float dx = ax - bx;
    float dy = ay - by;
    float dz = az - bz;
    return sqrtf(fmaf(dx, dx, fmaf(dy, dy, dz * dz)));
}

__global__ void __launch_bounds__(128)
rips_layer_kernel(const float* __restrict__ X,
                  const int* __restrict__ idx0_finite,    // [F0,3]
                  const int* __restrict__ idx1_finite,    // [F1,4] 16B rows
                  const int* __restrict__ idx1_essential, // [E1,2]
                  float* __restrict__ out,
                  int F0, int E0, int F1, int E1) {
    int i = blockIdx.x * blockDim.x + threadIdx.x;

    const int H0 = (F0 + 1) >> 1;  // dgm0 threads (2 rows each)
    const int T1 = H0;             // essential_dgm0 threads start
    const int T2 = T1 + E0;        // finite_dgm1 threads start
    const int T3 = T2 + F1;        // essential_dgm1 threads start
    const int total = T3 + E1;
    if (i >= total) return;

    const int o1 = 2 * F0;         // out: essential_dgm0 start
    const int o2 = o1 + E0;        // out: finite_dgm1 start
    const int o3 = o2 + 2 * F1;    // out: essential_dgm1 start

    if (i < T1) {
        // finite_dgm0 rows r0=2i, r1=2i+1: (0, dist(idx[3r+1], idx[3r+2]))
        int r0 = 2 * i;
        int r1 = r0 + 1;
        bool has2 = (r1 < F0);
        // front-batch all idx loads (independent)
        int a0 = __ldg(idx0_finite + 3 * r0 + 1);
        int b0 = __ldg(idx0_finite + 3 * r0 + 2);
        int a1 = 0, b1 = 0;
        if (has2) {
            a1 = __ldg(idx0_finite + 3 * r1 + 1);
            b1 = __ldg(idx0_finite + 3 * r1 + 2);
        }
        float d0 = pair_dist(X, a0, b0);
        reinterpret_cast<float2*>(out)[r0] = make_float2(0.0f, d0);
        if (has2) {
            float d1 = pair_dist(X, a1, b1);
            reinterpret_cast<float2*>(out)[r1] = make_float2(0.0f, d1);
        }
    } else if (i < T2) {
        // essential_dgm0: zero
        out[o1 + (i - T1)] = 0.0f;
    } else if (i < T3) {
        // finite_dgm1 row j: indices (a0,b0,a1,b1) in one 16B load
        int j = i - T2;
        int4 idx = __ldg(reinterpret_cast<const int4*>(idx1_finite) + j);
        float d0 = pair_dist(X, idx.x, idx.y);
        float d1 = pair_dist(X, idx.z, idx.w);
        out[o2 + 2 * j + 0] = d0;   // odd base offset -> scalar stores
        out[o2 + 2 * j + 1] = d1;
    } else {
        // essential_dgm1 row k
        int k = i - T3;
        int a = __ldg(idx1_essential + 2 * k + 0);
        int b = __ldg(idx1_essential + 2 * k + 1);
        out[o3 + k] = pair_dist(X, a, b);
    }
}

extern "C" void kernel_launch(void* const* d_in, const int* in_sizes, int n_in,
                              void* d_out, int out_size) {
    const float* X              = (const float*)d_in[0];
    const int*   idx0_finite    = (const int*)d_in[1];
    // d_in[2] = idx0_essential — only its COUNT matters (zeros in output)
    const int*   idx1_finite    = (const int*)d_in[3];
    const int*   idx1_essential = (const int*)d_in[4];

    int F0 = in_sizes[1] / 3;   // idx0_finite [F0,3]
    int E0 = in_sizes[2];       // idx0_essential [E0]
    int F1 = in_sizes[3] / 4;   // idx1_finite [F1,4]
    int E1 = in_sizes[4] / 2;   // idx1_essential [E1,2]

    int total_threads = ((F0 + 1) >> 1) + E0 + F1 + E1;

    const int threads = 128;
    int blocks = (total_threads + threads - 1) / threads;
    rips_layer_kernel<<<blocks, threads>>>(
        X, idx0_finite, idx1_finite, idx1_essential,
        (float*)d_out, F0, E0, F1, E1);
}

// round 8
// speedup vs baseline: 1.0048x; 1.0048x over previous
#include <cuda_runtime.h>

// RipsLayer: pure gather of pairwise distances at given index pairs.
//
// Output layout (flattened tuple order, fp32):
//   [0, 2*F0)      finite_dgm0 rows: (0, dist)     -> float2 stores
//   [2*F0, +E0)    essential_dgm0: zeros
//   [.., +2*F1)    finite_dgm1 rows: (dist, dist)  -> odd float offset when
//                  E0 is odd, so scalar stores
//   [.., +E1)      essential_dgm1: one dist per row
//
// Latency-bound at <1 wave: 1 row/thread, small CTAs (96 thr) to spread
// ~12.3K threads across the most SMs (129 CTAs), minimizing per-SM tail.

__device__ __forceinline__ float pair_dist(const float* __restrict__ X,
                                           int a, int b) {
    float ax = __ldg(X + 3 * a + 0);
    float ay = __ldg(X + 3 * a + 1);
    float az = __ldg(X + 3 * a + 2);
    float bx = __ldg(X + 3 * b + 0);
    float by = __ldg(X + 3 * b + 1);
    float bz = __ldg(X + 3 * b + 2);
    float dx = ax - bx;
    float dy = ay - by;
    float dz = az - bz;
    return sqrtf(fmaf(dx, dx, fmaf(dy, dy, dz * dz)));
}

__global__ void __launch_bounds__(96)
rips_layer_kernel(const float* __restrict__ X,
                  const int* __restrict__ idx0_finite,    // [F0,3]
                  const int* __restrict__ idx1_finite,    // [F1,4] 16B rows
                  const int* __restrict__ idx1_essential, // [E1,2]
                  float* __restrict__ out,
                  int F0, int E0, int F1, int E1) {
    int i = blockIdx.x * blockDim.x + threadIdx.x;

    const int T1 = F0;            // essential_dgm0 threads start
    const int T2 = T1 + E0;       // finite_dgm1 threads start
    const int T3 = T2 + F1;       // essential_dgm1 threads start
    const int total = T3 + E1;
    if (i >= total) return;

    const int o1 = 2 * F0;        // out: essential_dgm0 start
    const int o2 = o1 + E0;       // out: finite_dgm1 start
    const int o3 = o2 + 2 * F1;   // out: essential_dgm1 start

    if (i < T1) {
        // finite_dgm0 row i: (birth=0, death=dist(idx[3i+1], idx[3i+2]))
        int a = __ldg(idx0_finite + 3 * i + 1);
        int b = __ldg(idx0_finite + 3 * i + 2);
        float d = pair_dist(X, a, b);
        reinterpret_cast<float2*>(out)[i] = make_float2(0.0f, d);
    } else if (i < T2) {
        // essential_dgm0: zero
        out[o1 + (i - T1)] = 0.0f;
    } else if (i < T3) {
        // finite_dgm1 row j: indices (a0,b0,a1,b1) in one 16B load
        int j = i - T2;
        int4 idx = __ldg(reinterpret_cast<const int4*>(idx1_finite) + j);
        float d0 = pair_dist(X, idx.x, idx.y);
        float d1 = pair_dist(X, idx.z, idx.w);
        out[o2 + 2 * j + 0] = d0;   // odd base offset -> scalar stores
        out[o2 + 2 * j + 1] = d1;
    } else {
        // essential_dgm1 row k
        int k = i - T3;
        int a = __ldg(idx1_essential + 2 * k + 0);
        int b = __ldg(idx1_essential + 2 * k + 1);
        out[o3 + k] = pair_dist(X, a, b);
    }
}

extern "C" void kernel_launch(void* const* d_in, const int* in_sizes, int n_in,
                              void* d_out, int out_size) {
    const float* X              = (const float*)d_in[0];
    const int*   idx0_finite    = (const int*)d_in[1];
    // d_in[2] = idx0_essential — only its COUNT matters (zeros in output)
    const int*   idx1_finite    = (const int*)d_in[3];
    const int*   idx1_essential = (const int*)d_in[4];

    int F0 = in_sizes[1] / 3;   // idx0_finite [F0,3]
    int E0 = in_sizes[2];       // idx0_essential [E0]
    int F1 = in_sizes[3] / 4;   // idx1_finite [F1,4]
    int E1 = in_sizes[4] / 2;   // idx1_essential [E1,2]

    int total_threads = F0 + E0 + F1 + E1;

    const int threads = 96;     // 3 warps/CTA -> ~129 CTAs, max SM spread
    int blocks = (total_threads + threads - 1) / threads;
    rips_layer_kernel<<<blocks, threads>>>(
        X, idx0_finite, idx1_finite, idx1_essential,
        (float*)d_out, F0, E0, F1, E1);
}